// round 8
// baseline (speedup 1.0000x reference)
#include <cuda_runtime.h>
#include <cuda_bf16.h>
#include <cstdint>

#define Bb 4
#define Ss 1024
#define Dd 1024
#define Hh 16
#define DHh 64
#define SCALE 0.125f

// ---------------- scratch (device globals; no allocation allowed) ----------------
__device__ float g_Q[Bb * Hh * Ss * DHh];     // fp32 (lambda needs fp32 Q,K)
__device__ float g_K[Bb * Hh * Ss * DHh];
__device__ uint32_t g_Qt[Bb * Hh * Ss * DHh]; // tf32 bits
__device__ uint32_t g_Kt[Bb * Hh * Ss * DHh];
__device__ uint32_t g_Vt[Bb * Hh * Ss * DHh];
__device__ float g_CQ[Bb * Ss * DHh];
__device__ float g_CK[Bb * Ss * DHh];
__device__ float g_qsig[Bb * Ss * Ss];        // sigmoid quasi scores (head-invariant)
__device__ uint32_t g_Atf[Bb * Ss * Dd];      // tf32 hidden
__device__ uint32_t g_Wtf[3 * Dd * Dd];       // tf32 Wq|Wk|Wv

__device__ __forceinline__ float sigmoidf_(float x) { return 1.0f / (1.0f + __expf(-x)); }

__device__ __forceinline__ uint32_t f2tf(float x) {
    uint32_t r; asm("cvt.rna.tf32.f32 %0, %1;" : "=r"(r) : "f"(x)); return r;
}

__device__ __forceinline__ void mma_tf32(float* d, const uint32_t* a, const uint32_t* b) {
    asm volatile(
        "mma.sync.aligned.m16n8k8.row.col.f32.tf32.tf32.f32 "
        "{%0,%1,%2,%3}, {%4,%5,%6,%7}, {%8,%9}, {%0,%1,%2,%3};"
        : "+f"(d[0]), "+f"(d[1]), "+f"(d[2]), "+f"(d[3])
        : "r"(a[0]), "r"(a[1]), "r"(a[2]), "r"(a[3]), "r"(b[0]), "r"(b[1]));
}

__device__ __forceinline__ void cpa16(void* dst, const void* src) {
    uint32_t sa = (uint32_t)__cvta_generic_to_shared(dst);
    asm volatile("cp.async.cg.shared.global [%0], [%1], 16;" :: "r"(sa), "l"(src));
}

// ---------------- kernel 0: convert inputs to tf32 + CQ/CK GEMM -------------------
__global__ __launch_bounds__(256, 2) void cqck_conv(
    const float* __restrict__ A,
    const float* __restrict__ hidden,
    const float* __restrict__ Wq, const float* __restrict__ Wk, const float* __restrict__ Wv,
    const float* __restrict__ Wcq, const float* __restrict__ bcq,
    const float* __restrict__ Wck, const float* __restrict__ bck)
{
    {
        const int NT = 32 * 256;
        int t0 = blockIdx.x * 256 + threadIdx.x;
        const float4* hs = (const float4*)hidden;
        uint4* ad = (uint4*)g_Atf;
        for (int i = t0; i < (Bb * Ss * Dd) / 4; i += NT) {
            float4 v = hs[i];
            uint4 t = {f2tf(v.x), f2tf(v.y), f2tf(v.z), f2tf(v.w)};
            ad[i] = t;
        }
        const float* Ws[3] = {Wq, Wk, Wv};
        for (int wsel = 0; wsel < 3; wsel++) {
            const float4* s = (const float4*)Ws[wsel];
            uint4* d = (uint4*)(g_Wtf + wsel * (Dd * Dd));
            for (int i = t0; i < (Dd * Dd) / 4; i += NT) {
                float4 v = s[i];
                uint4 t = {f2tf(v.x), f2tf(v.y), f2tf(v.z), f2tf(v.w)};
                d[i] = t;
            }
        }
    }

    __shared__ uint32_t As[128][36];
    __shared__ uint32_t Bs[32][132];

    const int bm = blockIdx.x;
    const int tid = threadIdx.x;
    const int warpId = tid >> 5, lane = tid & 31;
    const int warpM = warpId & 1, warpN = warpId >> 1;
    const int gr = lane >> 2, gc = lane & 3;

    float acc[4][4][4];
#pragma unroll
    for (int i = 0; i < 4; i++)
#pragma unroll
        for (int j = 0; j < 4; j++)
#pragma unroll
            for (int t = 0; t < 4; t++) acc[i][j][t] = 0.0f;

    for (int k0 = 0; k0 < 1024; k0 += 32) {
#pragma unroll
        for (int i = 0; i < 4; i++) {
            int idx = tid + i * 256;
            int r = idx >> 3, c4 = idx & 7;
            float4 v = *(const float4*)&A[(size_t)(bm * 128 + r) * 1024 + k0 + c4 * 4];
            uint4 t = {f2tf(v.x), f2tf(v.y), f2tf(v.z), f2tf(v.w)};
            *(uint4*)&As[r][c4 * 4] = t;
        }
#pragma unroll
        for (int i = 0; i < 4; i++) {
            int idx = tid + i * 256;
            int row = idx >> 5;
            int c4  = idx & 31;
            int col = c4 * 4;
            const float* src = (col < 64)
                ? &Wcq[(size_t)(k0 + row) * 64 + col]
                : &Wck[(size_t)(k0 + row) * 64 + (col - 64)];
            float4 v = *(const float4*)src;
            uint4 t = {f2tf(v.x), f2tf(v.y), f2tf(v.z), f2tf(v.w)};
            *(uint4*)&Bs[row][col] = t;
        }
        __syncthreads();

#pragma unroll
        for (int ks = 0; ks < 4; ks++) {
            const int kb = ks * 8;
            uint32_t af[4][4];
#pragma unroll
            for (int mt = 0; mt < 4; mt++) {
                int m = warpM * 64 + mt * 16;
                af[mt][0] = As[m + gr][kb + gc];
                af[mt][1] = As[m + gr + 8][kb + gc];
                af[mt][2] = As[m + gr][kb + gc + 4];
                af[mt][3] = As[m + gr + 8][kb + gc + 4];
            }
            uint32_t bf[4][2];
#pragma unroll
            for (int nt = 0; nt < 4; nt++) {
                int n = warpN * 32 + nt * 8 + gr;
                bf[nt][0] = Bs[kb + gc][n];
                bf[nt][1] = Bs[kb + gc + 4][n];
            }
#pragma unroll
            for (int mt = 0; mt < 4; mt++)
#pragma unroll
                for (int nt = 0; nt < 4; nt++)
                    mma_tf32(acc[mt][nt], af[mt], bf[nt]);
        }
        __syncthreads();
    }

#pragma unroll
    for (int mt = 0; mt < 4; mt++) {
        int m0 = bm * 128 + warpM * 64 + mt * 16 + gr;
#pragma unroll
        for (int half = 0; half < 2; half++) {
            int m = m0 + half * 8;
#pragma unroll
            for (int nt = 0; nt < 4; nt++) {
                int n = warpN * 32 + nt * 8 + gc * 2;
                float2 v;
                if (n < 64) {
                    v.x = acc[mt][nt][half * 2 + 0] + bcq[n];
                    v.y = acc[mt][nt][half * 2 + 1] + bcq[n + 1];
                    *(float2*)&g_CQ[(size_t)m * 64 + n] = v;
                } else {
                    v.x = acc[mt][nt][half * 2 + 0] + bck[n - 64];
                    v.y = acc[mt][nt][half * 2 + 1] + bck[n - 63];
                    *(float2*)&g_CK[(size_t)m * 64 + (n - 64)] = v;
                }
            }
        }
    }
}

// ---------------- kernel 1: head-invariant quasi sigmoid [B,S,S] ------------------
__global__ __launch_bounds__(256) void qsig_kernel(const float* __restrict__ mask)
{
    __shared__ float Qs[64 * 68];
    __shared__ float Ks[64 * 68];
    const int bi = blockIdx.z, qt = blockIdx.y, kt = blockIdx.x;
    const int tid = threadIdx.x;
    const int tx = tid & 15, ty = tid >> 4;

#pragma unroll
    for (int i = 0; i < 4; i++) {
        int idx = tid + i * 256;
        int m = idx >> 4, c4 = idx & 15;
        float4 vq = *(const float4*)&g_CQ[((size_t)(bi * Ss + qt * 64 + m)) * 64 + c4 * 4];
        float4 vk = *(const float4*)&g_CK[((size_t)(bi * Ss + kt * 64 + m)) * 64 + c4 * 4];
        Qs[(c4 * 4 + 0) * 68 + m] = vq.x; Qs[(c4 * 4 + 1) * 68 + m] = vq.y;
        Qs[(c4 * 4 + 2) * 68 + m] = vq.z; Qs[(c4 * 4 + 3) * 68 + m] = vq.w;
        Ks[(c4 * 4 + 0) * 68 + m] = vk.x; Ks[(c4 * 4 + 1) * 68 + m] = vk.y;
        Ks[(c4 * 4 + 2) * 68 + m] = vk.z; Ks[(c4 * 4 + 3) * 68 + m] = vk.w;
    }
    __syncthreads();

    float acc[4][4];
#pragma unroll
    for (int i = 0; i < 4; i++)
#pragma unroll
        for (int j = 0; j < 4; j++) acc[i][j] = 0.0f;

#pragma unroll 4
    for (int d = 0; d < 64; d++) {
        float4 a4 = *(float4*)&Qs[d * 68 + ty * 4];
        float4 b4 = *(float4*)&Ks[d * 68 + tx * 4];
        float a[4] = {a4.x, a4.y, a4.z, a4.w};
        float bv[4] = {b4.x, b4.y, b4.z, b4.w};
#pragma unroll
        for (int i = 0; i < 4; i++)
#pragma unroll
            for (int j = 0; j < 4; j++) acc[i][j] += a[i] * bv[j];
    }
#pragma unroll
    for (int i = 0; i < 4; i++) {
        int qrow = qt * 64 + ty * 4 + i;
#pragma unroll
        for (int j = 0; j < 4; j++) {
            int kcol = kt * 64 + tx * 4 + j;
            float v = sigmoidf_(acc[i][j] * SCALE + mask[bi * Ss + kcol]);
            g_qsig[((size_t)(bi * Ss + qrow)) * Ss + kcol] = v;
        }
    }
}

// ---------------- kernel 2: pipelined tf32 projection GEMM (QKV, one grid) -------
#define PROJ_SMEM ((2 * 128 * 36 + 2 * 32 * 132) * 4)

__global__ __launch_bounds__(256, 2) void proj_mma(
    const float* __restrict__ bq, const float* __restrict__ bk, const float* __restrict__ bv)
{
    extern __shared__ uint32_t ps[];
    uint32_t* As = ps;
    uint32_t* Bs = ps + 2 * 128 * 36;

    const int which = blockIdx.z;
    const uint32_t* Wtf = g_Wtf + which * (Dd * Dd);
    const float* bias = (which == 0) ? bq : (which == 1) ? bk : bv;
    uint32_t* outt = (which == 0) ? g_Qt : (which == 1) ? g_Kt : g_Vt;
    float* outf = (which == 0) ? g_Q : g_K;

    const int bm = blockIdx.y, bn = blockIdx.x;
    const int tid = threadIdx.x;
    const int warpId = tid >> 5, lane = tid & 31;
    const int warpM = warpId & 1, warpN = warpId >> 1;
    const int gr = lane >> 2, gc = lane & 3;

    float acc[4][4][4];
#pragma unroll
    for (int i = 0; i < 4; i++)
#pragma unroll
        for (int j = 0; j < 4; j++)
#pragma unroll
            for (int t = 0; t < 4; t++) acc[i][j][t] = 0.0f;

    auto issue = [&](int st, int k0) {
#pragma unroll
        for (int i = 0; i < 4; i++) {
            int idx = tid + i * 256;
            int r = idx >> 3, c4 = idx & 7;
            cpa16(&As[st * 4608 + r * 36 + c4 * 4],
                  &g_Atf[(size_t)(bm * 128 + r) * 1024 + k0 + c4 * 4]);
        }
#pragma unroll
        for (int i = 0; i < 4; i++) {
            int idx = tid + i * 256;
            int row = idx >> 5, c4 = idx & 31;
            cpa16(&Bs[st * 4224 + row * 132 + c4 * 4],
                  &Wtf[(size_t)(k0 + row) * 1024 + bn * 128 + c4 * 4]);
        }
        asm volatile("cp.async.commit_group;");
    };

    issue(0, 0);

    for (int kt = 0; kt < 32; kt++) {
        if (kt < 31) {
            issue((kt + 1) & 1, (kt + 1) * 32);
            asm volatile("cp.async.wait_group 1;");
        } else {
            asm volatile("cp.async.wait_group 0;");
        }
        __syncthreads();

        const uint32_t* Ast = As + (kt & 1) * 4608;
        const uint32_t* Bst = Bs + (kt & 1) * 4224;
#pragma unroll
        for (int ks = 0; ks < 4; ks++) {
            const int kb = ks * 8;
            uint32_t af[4][4];
#pragma unroll
            for (int mt = 0; mt < 4; mt++) {
                int m = warpM * 64 + mt * 16;
                af[mt][0] = Ast[(m + gr) * 36 + kb + gc];
                af[mt][1] = Ast[(m + gr + 8) * 36 + kb + gc];
                af[mt][2] = Ast[(m + gr) * 36 + kb + gc + 4];
                af[mt][3] = Ast[(m + gr + 8) * 36 + kb + gc + 4];
            }
            uint32_t bf[4][2];
#pragma unroll
            for (int nt = 0; nt < 4; nt++) {
                int n = warpN * 32 + nt * 8 + gr;
                bf[nt][0] = Bst[(kb + gc) * 132 + n];
                bf[nt][1] = Bst[(kb + gc + 4) * 132 + n];
            }
#pragma unroll
            for (int mt = 0; mt < 4; mt++)
#pragma unroll
                for (int nt = 0; nt < 4; nt++)
                    mma_tf32(acc[mt][nt], af[mt], bf[nt]);
        }
        __syncthreads();
    }

#pragma unroll
    for (int mt = 0; mt < 4; mt++) {
        int m0 = bm * 128 + warpM * 64 + mt * 16 + gr;
#pragma unroll
        for (int half = 0; half < 2; half++) {
            int m = m0 + half * 8;
            int b = m >> 10, s = m & 1023;
#pragma unroll
            for (int nt = 0; nt < 4; nt++) {
                int n = bn * 128 + warpN * 32 + nt * 8 + gc * 2;
                int h = n >> 6, d = n & 63;
                size_t o = (((size_t)(b * Hh + h) * Ss + s)) * 64 + d;
                float2 v;
                v.x = acc[mt][nt][half * 2 + 0] + bias[n];
                v.y = acc[mt][nt][half * 2 + 1] + bias[n + 1];
                if (which < 2) *(float2*)&outf[o] = v;
                uint2 tv = {f2tf(v.x), f2tf(v.y)};
                *(uint2*)&outt[o] = tv;
            }
        }
    }
}

// ---------------- kernel 3: fused attention (16 q-rows, 2 blocks/SM) --------------
// smem (words): Sc[16][1028]=16448, Qtf[16][68]=1088, Ks[128][68]=8704 (reused as
// Vs[64][72]=4608), lam[16]. Total 26256 words = 105 KB -> 2 blocks/SM.
#define SC_STRIDE 1028
#define ATTN_WORDS (16 * SC_STRIDE + 16 * 68 + 128 * 68 + 16)
#define ATTN_SMEM (ATTN_WORDS * 4)

__global__ __launch_bounds__(256, 2) void attn_fused(
    const float* __restrict__ mask, float* __restrict__ out,
    const float* __restrict__ wlqc, const float* __restrict__ wlqq,
    const float* __restrict__ wlkc, const float* __restrict__ wlkk)
{
    extern __shared__ float sm[];
    float* Sc = sm;                                   // 16*1028
    uint32_t* Scu = (uint32_t*)Sc;
    uint32_t* Qtf = (uint32_t*)(Sc + 16 * SC_STRIDE); // 16*68
    uint32_t* Ks  = Qtf + 16 * 68;                    // 128*68 / Vs 64*72
    uint32_t* Vs  = Ks;
    float* lam_s  = (float*)(Ks + 128 * 68);          // 16

    const int qb = blockIdx.x;             // 0..63 (16-row tiles)
    const int bh = blockIdx.y;
    const int bi = bh >> 4, hi = bh & 15;
    const int tid = threadIdx.x;
    const int w = tid >> 5, lane = tid & 31;
    const int gr = lane >> 2, gc = lane & 3;

    const uint32_t* Qtg = &g_Qt[((size_t)bh * Ss + qb * 16) * 64];
    const uint32_t* Ktg = &g_Kt[(size_t)bh * Ss * 64];
    const uint32_t* Vtg = &g_Vt[(size_t)bh * Ss * 64];

    const size_t OFF_NEW   = (size_t)Bb * Ss * Dd;
    const size_t OFF_PROBS = OFF_NEW + (size_t)Bb * Hh * Ss * Ss;
    const size_t OFF_QUASI = OFF_PROBS + (size_t)Bb * Hh * Ss * Ss;

    // load Q tile [16][64] tf32 bits (256 threads = 16 rows x 16 uint4)
    {
        int m = tid >> 4, c4 = tid & 15;
        uint4 v = *(const uint4*)&Qtg[(size_t)m * 64 + c4 * 4];
        *(uint4*)&Qtf[m * 68 + c4 * 4] = v;
    }

    // lambda_context for the 16 q-rows (16 threads per row)
    {
        int r = tid >> 4;          // 0..15
        int j = tid & 15;          // 0..15
        int qrow = qb * 16 + r;
        const float* cq = &g_CQ[((size_t)(bi * Ss + qrow)) * 64];
        const float* ck = &g_CK[((size_t)(bi * Ss + qrow)) * 64];
        const float* qp = &g_Q[((size_t)bh * Ss + qrow) * 64];
        const float* kp = &g_K[((size_t)bh * Ss + qrow) * 64];
        float sq = 0.f, sk = 0.f;
#pragma unroll
        for (int d0 = 0; d0 < 4; d0++) {
            int d = j * 4 + d0;
            sq += cq[d] * wlqc[d] + qp[d] * wlqq[d];
            sk += ck[d] * wlkc[d] + kp[d] * wlkk[d];
        }
#pragma unroll
        for (int o = 8; o > 0; o >>= 1) {
            sq += __shfl_xor_sync(0xffffffffu, sq, o);
            sk += __shfl_xor_sync(0xffffffffu, sk, o);
        }
        if (j == 0) lam_s[r] = 1.0f - sigmoidf_(sq) - sigmoidf_(sk);
    }

    // ---------- Phase A (MMA): Sc[16][1024] = Q @ K^T * scale + mask ----------
    // 8 chunks of 128 K-rows; 8 warps each cover 16 cols (two n8 tiles).
    for (int nt = 0; nt < 8; nt++) {
#pragma unroll
        for (int i = 0; i < 8; i++) {
            int idx = tid + i * 256;          // 0..2047
            int n = idx >> 4, c4 = idx & 15;
            uint4 v = *(const uint4*)&Ktg[((size_t)(nt * 128 + n)) * 64 + c4 * 4];
            *(uint4*)&Ks[n * 68 + c4 * 4] = v;
        }
        __syncthreads();

        float acc[2][4];
#pragma unroll
        for (int t = 0; t < 2; t++)
#pragma unroll
            for (int e = 0; e < 4; e++) acc[t][e] = 0.0f;

#pragma unroll
        for (int ks = 0; ks < 8; ks++) {
            const int kb = ks * 8;
            uint32_t af[4];
            af[0] = Qtf[gr * 68 + kb + gc];
            af[1] = Qtf[(gr + 8) * 68 + kb + gc];
            af[2] = Qtf[gr * 68 + kb + gc + 4];
            af[3] = Qtf[(gr + 8) * 68 + kb + gc + 4];
#pragma unroll
            for (int t = 0; t < 2; t++) {
                int n0 = w * 16 + t * 8;
                uint32_t bf[2];
                bf[0] = Ks[(n0 + gr) * 68 + kb + gc];
                bf[1] = Ks[(n0 + gr) * 68 + kb + gc + 4];
                mma_tf32(acc[t], af, bf);
            }
        }

#pragma unroll
        for (int t = 0; t < 2; t++) {
            int col = nt * 128 + w * 16 + t * 8 + gc * 2;
            float mk0 = mask[bi * Ss + col];
            float mk1 = mask[bi * Ss + col + 1];
            float2 v0 = {acc[t][0] * SCALE + mk0, acc[t][1] * SCALE + mk1};
            float2 v1 = {acc[t][2] * SCALE + mk0, acc[t][3] * SCALE + mk1};
            *(float2*)&Sc[gr * SC_STRIDE + col] = v0;
            *(float2*)&Sc[(gr + 8) * SC_STRIDE + col] = v1;
        }
        __syncthreads();
    }

    // ---------- Phase B: softmax + quasi gating + prob writes ----------
    {
        for (int r = w * 2; r < w * 2 + 2; r++) {
            float mx = -1e30f;
            for (int c = lane; c < 1024; c += 32) mx = fmaxf(mx, Sc[r * SC_STRIDE + c]);
#pragma unroll
            for (int o = 16; o > 0; o >>= 1) mx = fmaxf(mx, __shfl_xor_sync(0xffffffffu, mx, o));
            float sum = 0.0f;
            for (int c = lane; c < 1024; c += 32) {
                float e = __expf(Sc[r * SC_STRIDE + c] - mx);
                Sc[r * SC_STRIDE + c] = e;
                sum += e;
            }
#pragma unroll
            for (int o = 16; o > 0; o >>= 1) sum += __shfl_xor_sync(0xffffffffu, sum, o);
            float inv = 1.0f / sum;

            const int qrow = qb * 16 + r;
            const float lam = lam_s[r];
            const float* qs_row = &g_qsig[((size_t)(bi * Ss + qrow)) * Ss];
            const size_t rowbase = ((size_t)bh * Ss + qrow) * Ss;
            float* probs_row = out + OFF_PROBS + rowbase;
            float* quasi_row = out + OFF_QUASI + rowbase;
            float* new_row   = out + OFF_NEW + rowbase;

            for (int c4 = lane; c4 < 256; c4 += 32) {
                float4 p = *(float4*)&Sc[r * SC_STRIDE + c4 * 4];
                p.x *= inv; p.y *= inv; p.z *= inv; p.w *= inv;
                float4 qs = *(const float4*)&qs_row[c4 * 4];
                float4 qp = {lam * qs.x, lam * qs.y, lam * qs.z, lam * qs.w};
                float4 np = {p.x + qp.x, p.y + qp.y, p.z + qp.z, p.w + qp.w};
                *(float4*)&probs_row[c4 * 4] = p;
                *(float4*)&quasi_row[c4 * 4] = qp;
                *(float4*)&new_row[c4 * 4] = np;
                // stash tf32 newP bits for phase C
                uint4 tp = {f2tf(np.x), f2tf(np.y), f2tf(np.z), f2tf(np.w)};
                *(uint4*)&Scu[r * SC_STRIDE + c4 * 4] = tp;
            }
        }
    }
    __syncthreads();

    // ---------- Phase C (MMA): ctx[16][64] = newP[16][1024] @ V[1024][64] ----------
    {
        float acc[4];
#pragma unroll
        for (int e = 0; e < 4; e++) acc[e] = 0.0f;

        for (int kt = 0; kt < 16; kt++) {
            // V chunk [64 kpos][64 d] tf32 bits -> Vs stride 72
#pragma unroll
            for (int i = 0; i < 4; i++) {
                int idx = tid + i * 256;
                int k = idx >> 4, c4 = idx & 15;
                uint4 v = *(const uint4*)&Vtg[((size_t)(kt * 64 + k)) * 64 + c4 * 4];
                *(uint4*)&Vs[k * 72 + c4 * 4] = v;
            }
            __syncthreads();

#pragma unroll
            for (int ks = 0; ks < 8; ks++) {
                int k0 = kt * 64 + ks * 8;
                uint32_t af[4];
                af[0] = Scu[gr * SC_STRIDE + k0 + gc];
                af[1] = Scu[(gr + 8) * SC_STRIDE + k0 + gc];
                af[2] = Scu[gr * SC_STRIDE + k0 + gc + 4];
                af[3] = Scu[(gr + 8) * SC_STRIDE + k0 + gc + 4];
                uint32_t bf[2];
                int n0 = w * 8;
                bf[0] = Vs[(ks * 8 + gc) * 72 + n0 + gr];
                bf[1] = Vs[(ks * 8 + gc + 4) * 72 + n0 + gr];
                mma_tf32(acc, af, bf);
            }
            __syncthreads();
        }

        int row0 = qb * 16 + gr;
        int col = hi * 64 + w * 8 + gc * 2;
        float2 v0 = {acc[0], acc[1]};
        float2 v1 = {acc[2], acc[3]};
        *(float2*)&out[((size_t)(bi * Ss + row0)) * Dd + col] = v0;
        *(float2*)&out[((size_t)(bi * Ss + row0 + 8)) * Dd + col] = v1;
    }
}

// ---------------- launch ----------------------------------------------------------
extern "C" void kernel_launch(void* const* d_in, const int* in_sizes, int n_in,
                              void* d_out, int out_size)
{
    (void)in_sizes; (void)n_in; (void)out_size;
    const float* hidden = (const float*)d_in[0];
    const float* mask   = (const float*)d_in[1];
    const float* ctxemb = (const float*)d_in[2];
    const float* Wq = (const float*)d_in[3];  const float* bq = (const float*)d_in[4];
    const float* Wk = (const float*)d_in[5];  const float* bk = (const float*)d_in[6];
    const float* Wv = (const float*)d_in[7];  const float* bv = (const float*)d_in[8];
    const float* Wcq = (const float*)d_in[9]; const float* bcq = (const float*)d_in[10];
    const float* Wck = (const float*)d_in[11];const float* bck = (const float*)d_in[12];
    const float* wlqc = (const float*)d_in[13];
    const float* wlqq = (const float*)d_in[14];
    const float* wlkc = (const float*)d_in[15];
    const float* wlkk = (const float*)d_in[16];
    float* out = (float*)d_out;

    cudaFuncSetAttribute(proj_mma, cudaFuncAttributeMaxDynamicSharedMemorySize, PROJ_SMEM);
    cudaFuncSetAttribute(attn_fused, cudaFuncAttributeMaxDynamicSharedMemorySize, ATTN_SMEM);

    // user launch index 3 = attn_fused (profiled by ncu)
    cqck_conv<<<32, 256>>>(ctxemb, hidden, Wq, Wk, Wv, Wcq, bcq, Wck, bck);   // 0
    qsig_kernel<<<dim3(16, 16, Bb), 256>>>(mask);                             // 1
    proj_mma<<<dim3(8, 32, 3), 256, PROJ_SMEM>>>(bq, bk, bv);                 // 2
    attn_fused<<<dim3(64, 64), 256, ATTN_SMEM>>>(mask, out, wlqc, wlqq, wlkc, wlkk); // 3
}

// round 9
// speedup vs baseline: 1.2849x; 1.2849x over previous
#include <cuda_runtime.h>
#include <cuda_bf16.h>
#include <cstdint>

#define Bb 4
#define Ss 1024
#define Dd 1024
#define Hh 16
#define DHh 64
#define SCALE 0.125f

// ---------------- scratch (device globals; no allocation allowed) ----------------
__device__ uint32_t g_Qt[Bb * Hh * Ss * DHh]; // tf32 bits [b][h][s][d]
__device__ uint32_t g_Kt[Bb * Hh * Ss * DHh];
__device__ uint32_t g_Vt[Bb * Hh * Ss * DHh];
__device__ float g_CQ[Bb * Ss * DHh];
__device__ float g_CK[Bb * Ss * DHh];
__device__ float g_qsig[Bb * Ss * Ss];        // sigmoid quasi scores (head-invariant)

__device__ __forceinline__ float sigmoidf_(float x) { return 1.0f / (1.0f + __expf(-x)); }

__device__ __forceinline__ uint32_t f2tf(float x) {
    uint32_t r; asm("cvt.rna.tf32.f32 %0, %1;" : "=r"(r) : "f"(x)); return r;
}

__device__ __forceinline__ void mma_tf32(float* d, const uint32_t* a, const uint32_t* b) {
    asm volatile(
        "mma.sync.aligned.m16n8k8.row.col.f32.tf32.tf32.f32 "
        "{%0,%1,%2,%3}, {%4,%5,%6,%7}, {%8,%9}, {%0,%1,%2,%3};"
        : "+f"(d[0]), "+f"(d[1]), "+f"(d[2]), "+f"(d[3])
        : "r"(a[0]), "r"(a[1]), "r"(a[2]), "r"(a[3]), "r"(b[0]), "r"(b[1]));
}

__device__ __forceinline__ void cpa16(void* dst, const void* src) {
    uint32_t sa = (uint32_t)__cvta_generic_to_shared(dst);
    asm volatile("cp.async.cg.shared.global [%0], [%1], 16;" :: "r"(sa), "l"(src));
}

// ---------------- kernel 0: tf32 MMA CQ|CK GEMM -----------------------------------
__global__ __launch_bounds__(256, 2) void cqck_mma(
    const float* __restrict__ A,
    const float* __restrict__ Wcq, const float* __restrict__ bcq,
    const float* __restrict__ Wck, const float* __restrict__ bck)
{
    __shared__ uint32_t As[128][36];
    __shared__ uint32_t Bs[32][132];

    const int bm = blockIdx.x;
    const int tid = threadIdx.x;
    const int warpId = tid >> 5, lane = tid & 31;
    const int warpM = warpId & 1, warpN = warpId >> 1;
    const int gr = lane >> 2, gc = lane & 3;

    float acc[4][4][4];
#pragma unroll
    for (int i = 0; i < 4; i++)
#pragma unroll
        for (int j = 0; j < 4; j++)
#pragma unroll
            for (int t = 0; t < 4; t++) acc[i][j][t] = 0.0f;

    for (int k0 = 0; k0 < 1024; k0 += 32) {
#pragma unroll
        for (int i = 0; i < 4; i++) {
            int idx = tid + i * 256;
            int r = idx >> 3, c4 = idx & 7;
            float4 v = *(const float4*)&A[(size_t)(bm * 128 + r) * 1024 + k0 + c4 * 4];
            uint4 t = {f2tf(v.x), f2tf(v.y), f2tf(v.z), f2tf(v.w)};
            *(uint4*)&As[r][c4 * 4] = t;
        }
#pragma unroll
        for (int i = 0; i < 4; i++) {
            int idx = tid + i * 256;
            int row = idx >> 5;               // 0..31
            int c4  = idx & 31;
            int col = c4 * 4;
            const float* src = (col < 64)
                ? &Wcq[(size_t)(k0 + row) * 64 + col]
                : &Wck[(size_t)(k0 + row) * 64 + (col - 64)];
            float4 v = *(const float4*)src;
            uint4 t = {f2tf(v.x), f2tf(v.y), f2tf(v.z), f2tf(v.w)};
            *(uint4*)&Bs[row][col] = t;
        }
        __syncthreads();

#pragma unroll
        for (int ks = 0; ks < 4; ks++) {
            const int kb = ks * 8;
            uint32_t af[4][4];
#pragma unroll
            for (int mt = 0; mt < 4; mt++) {
                int m = warpM * 64 + mt * 16;
                af[mt][0] = As[m + gr][kb + gc];
                af[mt][1] = As[m + gr + 8][kb + gc];
                af[mt][2] = As[m + gr][kb + gc + 4];
                af[mt][3] = As[m + gr + 8][kb + gc + 4];
            }
            uint32_t bf[4][2];
#pragma unroll
            for (int nt = 0; nt < 4; nt++) {
                int n = warpN * 32 + nt * 8 + gr;
                bf[nt][0] = Bs[kb + gc][n];
                bf[nt][1] = Bs[kb + gc + 4][n];
            }
#pragma unroll
            for (int mt = 0; mt < 4; mt++)
#pragma unroll
                for (int nt = 0; nt < 4; nt++)
                    mma_tf32(acc[mt][nt], af[mt], bf[nt]);
        }
        __syncthreads();
    }

#pragma unroll
    for (int mt = 0; mt < 4; mt++) {
        int m0 = bm * 128 + warpM * 64 + mt * 16 + gr;
#pragma unroll
        for (int half = 0; half < 2; half++) {
            int m = m0 + half * 8;
#pragma unroll
            for (int nt = 0; nt < 4; nt++) {
                int n = warpN * 32 + nt * 8 + gc * 2;
                float2 v;
                if (n < 64) {
                    v.x = acc[mt][nt][half * 2 + 0] + bcq[n];
                    v.y = acc[mt][nt][half * 2 + 1] + bcq[n + 1];
                    *(float2*)&g_CQ[(size_t)m * 64 + n] = v;
                } else {
                    v.x = acc[mt][nt][half * 2 + 0] + bck[n - 64];
                    v.y = acc[mt][nt][half * 2 + 1] + bck[n - 63];
                    *(float2*)&g_CK[(size_t)m * 64 + (n - 64)] = v;
                }
            }
        }
    }
}

// ---------------- kernel 1: head-invariant quasi sigmoid [B,S,S] ------------------
__global__ __launch_bounds__(256) void qsig_kernel(const float* __restrict__ mask)
{
    __shared__ float Qs[64 * 68];
    __shared__ float Ks[64 * 68];
    const int bi = blockIdx.z, qt = blockIdx.y, kt = blockIdx.x;
    const int tid = threadIdx.x;
    const int tx = tid & 15, ty = tid >> 4;

#pragma unroll
    for (int i = 0; i < 4; i++) {
        int idx = tid + i * 256;
        int m = idx >> 4, c4 = idx & 15;
        float4 vq = *(const float4*)&g_CQ[((size_t)(bi * Ss + qt * 64 + m)) * 64 + c4 * 4];
        float4 vk = *(const float4*)&g_CK[((size_t)(bi * Ss + kt * 64 + m)) * 64 + c4 * 4];
        Qs[(c4 * 4 + 0) * 68 + m] = vq.x; Qs[(c4 * 4 + 1) * 68 + m] = vq.y;
        Qs[(c4 * 4 + 2) * 68 + m] = vq.z; Qs[(c4 * 4 + 3) * 68 + m] = vq.w;
        Ks[(c4 * 4 + 0) * 68 + m] = vk.x; Ks[(c4 * 4 + 1) * 68 + m] = vk.y;
        Ks[(c4 * 4 + 2) * 68 + m] = vk.z; Ks[(c4 * 4 + 3) * 68 + m] = vk.w;
    }
    __syncthreads();

    float acc[4][4];
#pragma unroll
    for (int i = 0; i < 4; i++)
#pragma unroll
        for (int j = 0; j < 4; j++) acc[i][j] = 0.0f;

#pragma unroll 4
    for (int d = 0; d < 64; d++) {
        float4 a4 = *(float4*)&Qs[d * 68 + ty * 4];
        float4 b4 = *(float4*)&Ks[d * 68 + tx * 4];
        float a[4] = {a4.x, a4.y, a4.z, a4.w};
        float bv[4] = {b4.x, b4.y, b4.z, b4.w};
#pragma unroll
        for (int i = 0; i < 4; i++)
#pragma unroll
            for (int j = 0; j < 4; j++) acc[i][j] += a[i] * bv[j];
    }
#pragma unroll
    for (int i = 0; i < 4; i++) {
        int qrow = qt * 64 + ty * 4 + i;
#pragma unroll
        for (int j = 0; j < 4; j++) {
            int kcol = kt * 64 + tx * 4 + j;
            float v = sigmoidf_(acc[i][j] * SCALE + mask[bi * Ss + kcol]);
            g_qsig[((size_t)(bi * Ss + qrow)) * Ss + kcol] = v;
        }
    }
}

// ---------------- kernel 2: tf32 projection GEMM, inline cvt, grid z=3 -----------
__global__ __launch_bounds__(256, 2) void proj_mma(
    const float* __restrict__ hidden,
    const float* __restrict__ Wq, const float* __restrict__ Wk, const float* __restrict__ Wv,
    const float* __restrict__ bq, const float* __restrict__ bk, const float* __restrict__ bv)
{
    __shared__ uint32_t As[128][36];
    __shared__ uint32_t Bs[32][132];

    const int which = blockIdx.z;
    const float* W = (which == 0) ? Wq : (which == 1) ? Wk : Wv;
    const float* bias = (which == 0) ? bq : (which == 1) ? bk : bv;
    uint32_t* outt = (which == 0) ? g_Qt : (which == 1) ? g_Kt : g_Vt;

    const int bm = blockIdx.y, bn = blockIdx.x;
    const int tid = threadIdx.x;
    const int warpId = tid >> 5, lane = tid & 31;
    const int warpM = warpId & 1, warpN = warpId >> 1;
    const int gr = lane >> 2, gc = lane & 3;

    float acc[4][4][4];
#pragma unroll
    for (int i = 0; i < 4; i++)
#pragma unroll
        for (int j = 0; j < 4; j++)
#pragma unroll
            for (int t = 0; t < 4; t++) acc[i][j][t] = 0.0f;

    for (int k0 = 0; k0 < 1024; k0 += 32) {
#pragma unroll
        for (int i = 0; i < 4; i++) {
            int idx = tid + i * 256;
            int r = idx >> 3, c4 = idx & 7;
            float4 v = *(const float4*)&hidden[(size_t)(bm * 128 + r) * 1024 + k0 + c4 * 4];
            uint4 t = {f2tf(v.x), f2tf(v.y), f2tf(v.z), f2tf(v.w)};
            *(uint4*)&As[r][c4 * 4] = t;
        }
#pragma unroll
        for (int i = 0; i < 4; i++) {
            int idx = tid + i * 256;
            int row = idx >> 5, c4 = idx & 31;
            float4 v = *(const float4*)&W[(size_t)(k0 + row) * 1024 + bn * 128 + c4 * 4];
            uint4 t = {f2tf(v.x), f2tf(v.y), f2tf(v.z), f2tf(v.w)};
            *(uint4*)&Bs[row][c4 * 4] = t;
        }
        __syncthreads();

#pragma unroll
        for (int ks = 0; ks < 4; ks++) {
            const int kb = ks * 8;
            uint32_t af[4][4];
#pragma unroll
            for (int mt = 0; mt < 4; mt++) {
                int m = warpM * 64 + mt * 16;
                af[mt][0] = As[m + gr][kb + gc];
                af[mt][1] = As[m + gr + 8][kb + gc];
                af[mt][2] = As[m + gr][kb + gc + 4];
                af[mt][3] = As[m + gr + 8][kb + gc + 4];
            }
            uint32_t bf[4][2];
#pragma unroll
            for (int nt = 0; nt < 4; nt++) {
                int n = warpN * 32 + nt * 8 + gr;
                bf[nt][0] = Bs[kb + gc][n];
                bf[nt][1] = Bs[kb + gc + 4][n];
            }
#pragma unroll
            for (int mt = 0; mt < 4; mt++)
#pragma unroll
                for (int nt = 0; nt < 4; nt++)
                    mma_tf32(acc[mt][nt], af[mt], bf[nt]);
        }
        __syncthreads();
    }

    // epilogue: scatter tf32 bits to [B,H,S,DH]
#pragma unroll
    for (int mt = 0; mt < 4; mt++) {
        int m0 = bm * 128 + warpM * 64 + mt * 16 + gr;
#pragma unroll
        for (int half = 0; half < 2; half++) {
            int m = m0 + half * 8;
            int b = m >> 10, s = m & 1023;
#pragma unroll
            for (int nt = 0; nt < 4; nt++) {
                int n = bn * 128 + warpN * 32 + nt * 8 + gc * 2;
                int h = n >> 6, d = n & 63;
                size_t o = (((size_t)(b * Hh + h) * Ss + s)) * 64 + d;
                uint2 tv = {f2tf(acc[mt][nt][half * 2 + 0] + bias[n]),
                            f2tf(acc[mt][nt][half * 2 + 1] + bias[n + 1])};
                *(uint2*)&outt[o] = tv;
            }
        }
    }
}

// ---------------- kernel 3: attention phases A+B (512 threads, 32 q-rows) ---------
#define SC_STRIDE 1028
#define ATTN_WORDS (32 * SC_STRIDE + 32 * 68 + 256 * 68 + 32)
#define ATTN_SMEM (ATTN_WORDS * 4)

__global__ __launch_bounds__(512, 1) void attn_ab(
    const float* __restrict__ mask, float* __restrict__ out,
    const float* __restrict__ wlqc, const float* __restrict__ wlqq,
    const float* __restrict__ wlkc, const float* __restrict__ wlkk)
{
    extern __shared__ float sm[];
    float* Sc = sm;                                   // 32*1028
    uint32_t* Qtf = (uint32_t*)(Sc + 32 * SC_STRIDE); // 32*68
    uint32_t* Ks  = Qtf + 32 * 68;                    // 256*68
    float* lam_s  = (float*)(Ks + 256 * 68);          // 32

    const int qb = blockIdx.x;
    const int bh = blockIdx.y;
    const int bi = bh >> 4;
    const int tid = threadIdx.x;
    const int w = tid >> 5, lane = tid & 31;
    const int gr = lane >> 2, gc = lane & 3;
    const int wm = w >> 3, wn = w & 7;     // 2 x 8 warp grid

    const uint32_t* Qtg = &g_Qt[((size_t)bh * Ss + qb * 32) * 64];
    const uint32_t* Ktg = &g_Kt[(size_t)bh * Ss * 64];

    const size_t OFF_NEW   = (size_t)Bb * Ss * Dd;
    const size_t OFF_PROBS = OFF_NEW + (size_t)Bb * Hh * Ss * Ss;
    const size_t OFF_QUASI = OFF_PROBS + (size_t)Bb * Hh * Ss * Ss;

    // load Q tile [32][64] tf32 bits
    {
        int m = tid >> 4, c4 = tid & 15;
        uint4 v = *(const uint4*)&Qtg[(size_t)m * 64 + c4 * 4];
        *(uint4*)&Qtf[m * 68 + c4 * 4] = v;
    }

    // inline lambda_context (tf32 bits reinterpret as fp32 — err ~5e-5, negligible)
    {
        int r = tid >> 4;          // 0..31
        int j = tid & 15;          // 0..15
        int qrow = qb * 32 + r;
        const float* cq = &g_CQ[((size_t)(bi * Ss + qrow)) * 64];
        const float* ck = &g_CK[((size_t)(bi * Ss + qrow)) * 64];
        const uint32_t* qp = &g_Qt[((size_t)bh * Ss + qrow) * 64];
        const uint32_t* kp = &g_Kt[((size_t)bh * Ss + qrow) * 64];
        float sq = 0.f, sk = 0.f;
#pragma unroll
        for (int d0 = 0; d0 < 4; d0++) {
            int d = j * 4 + d0;
            sq += cq[d] * wlqc[d] + __uint_as_float(qp[d]) * wlqq[d];
            sk += ck[d] * wlkc[d] + __uint_as_float(kp[d]) * wlkk[d];
        }
#pragma unroll
        for (int o = 8; o > 0; o >>= 1) {
            sq += __shfl_xor_sync(0xffffffffu, sq, o);
            sk += __shfl_xor_sync(0xffffffffu, sk, o);
        }
        if (j == 0) lam_s[r] = 1.0f - sigmoidf_(sq) - sigmoidf_(sk);
    }

    // ---------- Phase A (MMA): Sc[32][1024] = Q @ K^T * scale + mask ----------
    for (int nt = 0; nt < 4; nt++) {
#pragma unroll
        for (int i = 0; i < 8; i++) {
            int idx = tid + i * 512;
            int n = idx >> 4, c4 = idx & 15;
            uint4 v = *(const uint4*)&Ktg[((size_t)(nt * 256 + n)) * 64 + c4 * 4];
            *(uint4*)&Ks[n * 68 + c4 * 4] = v;
        }
        __syncthreads();

        float acc[4][4];
#pragma unroll
        for (int t = 0; t < 4; t++)
#pragma unroll
            for (int e = 0; e < 4; e++) acc[t][e] = 0.0f;

#pragma unroll
        for (int ks = 0; ks < 8; ks++) {
            const int kb = ks * 8;
            uint32_t af[4];
            int m0 = wm * 16;
            af[0] = Qtf[(m0 + gr) * 68 + kb + gc];
            af[1] = Qtf[(m0 + gr + 8) * 68 + kb + gc];
            af[2] = Qtf[(m0 + gr) * 68 + kb + gc + 4];
            af[3] = Qtf[(m0 + gr + 8) * 68 + kb + gc + 4];
#pragma unroll
            for (int t = 0; t < 4; t++) {
                int n0 = wn * 32 + t * 8;
                uint32_t bf[2];
                bf[0] = Ks[(n0 + gr) * 68 + kb + gc];
                bf[1] = Ks[(n0 + gr) * 68 + kb + gc + 4];
                mma_tf32(acc[t], af, bf);
            }
        }

#pragma unroll
        for (int t = 0; t < 4; t++) {
            int row0 = wm * 16 + gr;
            int col = nt * 256 + wn * 32 + t * 8 + gc * 2;
            float mk0 = mask[bi * Ss + col];
            float mk1 = mask[bi * Ss + col + 1];
            float2 v0 = {acc[t][0] * SCALE + mk0, acc[t][1] * SCALE + mk1};
            float2 v1 = {acc[t][2] * SCALE + mk0, acc[t][3] * SCALE + mk1};
            *(float2*)&Sc[row0 * SC_STRIDE + col] = v0;
            *(float2*)&Sc[(row0 + 8) * SC_STRIDE + col] = v1;
        }
        __syncthreads();
    }

    // ---------- Phase B: softmax + quasi gating + prob writes ----------
    {
        for (int r = w * 2; r < w * 2 + 2; r++) {
            float mx = -1e30f;
            for (int c = lane; c < 1024; c += 32) mx = fmaxf(mx, Sc[r * SC_STRIDE + c]);
#pragma unroll
            for (int o = 16; o > 0; o >>= 1) mx = fmaxf(mx, __shfl_xor_sync(0xffffffffu, mx, o));
            float sum = 0.0f;
            for (int c = lane; c < 1024; c += 32) {
                float e = __expf(Sc[r * SC_STRIDE + c] - mx);
                Sc[r * SC_STRIDE + c] = e;
                sum += e;
            }
#pragma unroll
            for (int o = 16; o > 0; o >>= 1) sum += __shfl_xor_sync(0xffffffffu, sum, o);
            float inv = 1.0f / sum;

            const int qrow = qb * 32 + r;
            const float lam = lam_s[r];
            const float* qs_row = &g_qsig[((size_t)(bi * Ss + qrow)) * Ss];
            const size_t rowbase = ((size_t)bh * Ss + qrow) * Ss;
            float* probs_row = out + OFF_PROBS + rowbase;
            float* quasi_row = out + OFF_QUASI + rowbase;
            float* new_row   = out + OFF_NEW + rowbase;

            for (int c4 = lane; c4 < 256; c4 += 32) {
                float4 p = *(float4*)&Sc[r * SC_STRIDE + c4 * 4];
                p.x *= inv; p.y *= inv; p.z *= inv; p.w *= inv;
                float4 qs = *(const float4*)&qs_row[c4 * 4];
                float4 qp = {lam * qs.x, lam * qs.y, lam * qs.z, lam * qs.w};
                float4 np = {p.x + qp.x, p.y + qp.y, p.z + qp.z, p.w + qp.w};
                *(float4*)&probs_row[c4 * 4] = p;
                *(float4*)&quasi_row[c4 * 4] = qp;
                *(float4*)&new_row[c4 * 4] = np;
            }
        }
    }
}

// ---------------- kernel 4: ctx = newP @ V, cp.async 2-stage ----------------------
// stages: Ps (fp32 raw) [2][128][36], Vs (tf32 bits) [2][32][72]; BK=32, 32 chunks.
#define PV_SMEM ((2 * 128 * 36 + 2 * 32 * 72) * 4)

__global__ __launch_bounds__(256) void pv_gemm(float* __restrict__ out)
{
    extern __shared__ uint32_t pvs[];
    float*    Psf = (float*)pvs;            // 2 x 128*36
    uint32_t* Vs  = pvs + 2 * 128 * 36;     // 2 x 32*72

    const int qt = blockIdx.x;        // 0..7
    const int bh = blockIdx.y;
    const int bi = bh >> 4, hi = bh & 15;
    const int tid = threadIdx.x;
    const int warpId = tid >> 5, lane = tid & 31;
    const int wm = warpId & 3, wn = warpId >> 2;
    const int gr = lane >> 2, gc = lane & 3;

    const size_t OFF_NEW = (size_t)Bb * Ss * Dd;
    const float* newb = out + OFF_NEW + ((size_t)bh * Ss + qt * 128) * Ss;
    const uint32_t* Vtg = &g_Vt[(size_t)bh * Ss * 64];

    float acc[2][4][4];
#pragma unroll
    for (int m = 0; m < 2; m++)
#pragma unroll
        for (int t = 0; t < 4; t++)
#pragma unroll
            for (int e = 0; e < 4; e++) acc[m][t][e] = 0.0f;

    auto issue = [&](int st, int kt) {
        // P chunk: 128 rows x 32 cols fp32
#pragma unroll
        for (int i = 0; i < 4; i++) {
            int idx = tid + i * 256;          // 0..1023
            int r = idx >> 3, c4 = idx & 7;
            cpa16(&Psf[st * 4608 + r * 36 + c4 * 4],
                  &newb[(size_t)r * 1024 + kt * 32 + c4 * 4]);
        }
        // V chunk: 32 kpos x 64 d tf32 bits
#pragma unroll
        for (int i = 0; i < 2; i++) {
            int idx = tid + i * 256;          // 0..511
            int k = idx >> 4, c4 = idx & 15;
            cpa16(&Vs[st * 2304 + k * 72 + c4 * 4],
                  &Vtg[((size_t)(kt * 32 + k)) * 64 + c4 * 4]);
        }
        asm volatile("cp.async.commit_group;");
    };

    issue(0, 0);

    for (int kt = 0; kt < 32; kt++) {
        if (kt < 31) {
            issue((kt + 1) & 1, kt + 1);
            asm volatile("cp.async.wait_group 1;");
        } else {
            asm volatile("cp.async.wait_group 0;");
        }
        __syncthreads();

        const float* Pst = Psf + (kt & 1) * 4608;
        const uint32_t* Vst = Vs + (kt & 1) * 2304;
#pragma unroll
        for (int ks = 0; ks < 4; ks++) {
            const int kb = ks * 8;
            uint32_t af[2][4];
#pragma unroll
            for (int m = 0; m < 2; m++) {
                int m0 = wm * 32 + m * 16;
                af[m][0] = f2tf(Pst[(m0 + gr) * 36 + kb + gc]);
                af[m][1] = f2tf(Pst[(m0 + gr + 8) * 36 + kb + gc]);
                af[m][2] = f2tf(Pst[(m0 + gr) * 36 + kb + gc + 4]);
                af[m][3] = f2tf(Pst[(m0 + gr + 8) * 36 + kb + gc + 4]);
            }
#pragma unroll
            for (int t = 0; t < 4; t++) {
                int n0 = wn * 32 + t * 8;
                uint32_t bf[2];
                bf[0] = Vst[(kb + gc) * 72 + n0 + gr];
                bf[1] = Vst[(kb + gc + 4) * 72 + n0 + gr];
                mma_tf32(acc[0][t], af[0], bf);
                mma_tf32(acc[1][t], af[1], bf);
            }
        }
        __syncthreads();
    }

#pragma unroll
    for (int m = 0; m < 2; m++) {
        int row0 = qt * 128 + wm * 32 + m * 16 + gr;
#pragma unroll
        for (int t = 0; t < 4; t++) {
            int col = hi * 64 + wn * 32 + t * 8 + gc * 2;
            float2 v0 = {acc[m][t][0], acc[m][t][1]};
            float2 v1 = {acc[m][t][2], acc[m][t][3]};
            *(float2*)&out[((size_t)(bi * Ss + row0)) * Dd + col] = v0;
            *(float2*)&out[((size_t)(bi * Ss + row0 + 8)) * Dd + col] = v1;
        }
    }
}

// ---------------- launch ----------------------------------------------------------
extern "C" void kernel_launch(void* const* d_in, const int* in_sizes, int n_in,
                              void* d_out, int out_size)
{
    (void)in_sizes; (void)n_in; (void)out_size;
    const float* hidden = (const float*)d_in[0];
    const float* mask   = (const float*)d_in[1];
    const float* ctxemb = (const float*)d_in[2];
    const float* Wq = (const float*)d_in[3];  const float* bq = (const float*)d_in[4];
    const float* Wk = (const float*)d_in[5];  const float* bk = (const float*)d_in[6];
    const float* Wv = (const float*)d_in[7];  const float* bv = (const float*)d_in[8];
    const float* Wcq = (const float*)d_in[9]; const float* bcq = (const float*)d_in[10];
    const float* Wck = (const float*)d_in[11];const float* bck = (const float*)d_in[12];
    const float* wlqc = (const float*)d_in[13];
    const float* wlqq = (const float*)d_in[14];
    const float* wlkc = (const float*)d_in[15];
    const float* wlkk = (const float*)d_in[16];
    float* out = (float*)d_out;

    cudaFuncSetAttribute(attn_ab, cudaFuncAttributeMaxDynamicSharedMemorySize, ATTN_SMEM);
    cudaFuncSetAttribute(pv_gemm, cudaFuncAttributeMaxDynamicSharedMemorySize, PV_SMEM);

    // user launch index 3 = attn_ab (profiled by ncu)
    cqck_mma<<<32, 256>>>(ctxemb, Wcq, bcq, Wck, bck);                        // 0
    qsig_kernel<<<dim3(16, 16, Bb), 256>>>(mask);                             // 1
    proj_mma<<<dim3(8, 32, 3), 256>>>(hidden, Wq, Wk, Wv, bq, bk, bv);        // 2
    attn_ab<<<dim3(32, 64), 512, ATTN_SMEM>>>(mask, out, wlqc, wlqq, wlkc, wlkk); // 3
    pv_gemm<<<dim3(8, 64), 256, PV_SMEM>>>(out);                              // 4
}